// round 11
// baseline (speedup 1.0000x reference)
#include <cuda_runtime.h>

// Problem constants
#define D_H      512
#define D_MODEL  2048
#define BB       4
#define TT       4096
#define O4       (D_MODEL / 4)     // 512 float4 columns per row

#define G        592               // 4 blocks x 148 SMs, exactly co-resident
#define NT       256               // threads per block
#define GEMM_G   512               // blocks participating in GEMV phases

#define NKM      64
#define KCM      (D_H / NKM)       // 8 rows per k-chunk (phase 1)
#define NKV      64
#define KCV      (D_MODEL / NKV)   // 32 rows per k-chunk (phases 2,3)

// Stream phase: static balanced split of 16384 rows over 592 blocks
#define NROWS    (BB * TT)                         // 16384
#define RPB_LO   (NROWS / G)                       // 27
#define RPB_REM  (NROWS - RPB_LO * G)              // 400 blocks get 28

// Scratch (__device__ globals; no allocation allowed)
__device__ __align__(16) float g_PM [NKM * BB * D_MODEL];   // 2 MB
__device__ __align__(16) float g_PV [NKV * BB * D_MODEL];   // 2 MB
__device__ __align__(16) float g_POV[NKV * BB * D_MODEL];   // 2 MB
__device__ __align__(16) float g_OV [BB * D_MODEL];         // 32 KB
__device__ unsigned g_bar;                                  // monotonic barrier counter

// Grid barrier: monotonic counter, base captured at kernel entry.
// Arrival: one atomicAdd per block. Wait: PLAIN VOLATILE LOAD polling (no RMW
// -- polling with atomicAdd(p,0) serializes the LTS atomic ALU and starves
// the arrival atomics; a load does not). Graph-replay safe (counter only
// advances; 4*G per launch).
__device__ __forceinline__ void grid_bar(unsigned base, unsigned phase) {
    __syncthreads();
    if (threadIdx.x == 0) {
        __threadfence();
        atomicAdd(&g_bar, 1u);
        const unsigned tgt = base + phase * G;
        const volatile unsigned* p = (const volatile unsigned*)&g_bar;
        while (*p < tgt) __nanosleep(64);
        __threadfence();
    }
    __syncthreads();
}

__global__ void __launch_bounds__(NT, 4) k_fused(
    const float* __restrict__ lh,  const float* __restrict__ zH,
    const float* __restrict__ Wm,  const float* __restrict__ Wv,
    const float* __restrict__ Wo,  const float* __restrict__ gate,
    float* __restrict__ out)
{
    __shared__ float xs[BB][KCV];        // staging (phases 1-3)
    __shared__ unsigned s_base;
    const int tid = threadIdx.x;
    const int bid = blockIdx.x;

    if (tid == 0)  // round down to the 4*G boundary of this launch
        s_base = (atomicAdd(&g_bar, 0u) / (4u * G)) * (4u * G);
    __syncthreads();
    const unsigned base = s_base;

    const bool gemv = (bid < GEMM_G);
    const int oc   = bid & 7;            // 8 o-chunks of 64 float4 columns
    const int kc   = bid >> 3;           // 64 k-chunks (for gemv blocks)
    const int lane = tid & 63;
    const int b    = tid >> 6;
    const int o4   = oc * 64 + lane;

    // ---- Phase 1: PM[kc][b][o] = sum_{i in chunk} zH[b,i] * W_mem[i,o] ----
    if (gemv) {
        if (tid < BB * KCM) {            // 32 staged values
            int bb = tid >> 3, j = tid & 7;
            xs[bb][j] = zH[bb * D_H + kc * KCM + j];
        }
        __syncthreads();
        const float4* W4 = reinterpret_cast<const float4*>(Wm)
                         + (size_t)(kc * KCM) * O4 + o4;
        float4 a = {0.f, 0.f, 0.f, 0.f};
        #pragma unroll
        for (int j = 0; j < KCM; ++j) {
            float4 w = W4[(size_t)j * O4];
            float  x = xs[b][j];
            a.x += x * w.x; a.y += x * w.y; a.z += x * w.z; a.w += x * w.w;
        }
        reinterpret_cast<float4*>(g_PM)[((size_t)kc * BB + b) * O4 + o4] = a;
    }
    grid_bar(base, 1);

    // ---- Phase 2: PV[kc][b][o] = sum_{i in chunk} mem[b,i] * W_v[i,o] ----
    if (gemv) {
        if (tid < BB * KCV) {            // 128 staged; fold 64 PM partials (L2-hot)
            int bb = tid >> 5, j = tid & 31;
            int col = kc * KCV + j;
            float s = 0.f;
            #pragma unroll
            for (int p = 0; p < NKM; ++p)
                s += g_PM[((size_t)p * BB + bb) * D_MODEL + col];
            xs[bb][j] = s;
        }
        __syncthreads();
        const float4* W4 = reinterpret_cast<const float4*>(Wv)
                         + (size_t)(kc * KCV) * O4 + o4;
        float4 a = {0.f, 0.f, 0.f, 0.f};
        #pragma unroll 16
        for (int j = 0; j < KCV; ++j) {
            float4 w = W4[(size_t)j * O4];
            float  x = xs[b][j];
            a.x += x * w.x; a.y += x * w.y; a.z += x * w.z; a.w += x * w.w;
        }
        reinterpret_cast<float4*>(g_PV)[((size_t)kc * BB + b) * O4 + o4] = a;
    }
    grid_bar(base, 2);

    // ---- Phase 3: POV[kc][b][o] = sum_{i in chunk} V[b,i] * W_o[i,o] ----
    if (gemv) {
        if (tid < BB * KCV) {
            int bb = tid >> 5, j = tid & 31;
            int col = kc * KCV + j;
            float s = 0.f;
            #pragma unroll
            for (int p = 0; p < NKV; ++p)
                s += g_PV[((size_t)p * BB + bb) * D_MODEL + col];
            xs[bb][j] = s;
        }
        __syncthreads();
        const float4* W4 = reinterpret_cast<const float4*>(Wo)
                         + (size_t)(kc * KCV) * O4 + o4;
        float4 a = {0.f, 0.f, 0.f, 0.f};
        #pragma unroll 16
        for (int j = 0; j < KCV; ++j) {
            float4 w = W4[(size_t)j * O4];
            float  x = xs[b][j];
            a.x += x * w.x; a.y += x * w.y; a.z += x * w.z; a.w += x * w.w;
        }
        reinterpret_cast<float4*>(g_POV)[((size_t)kc * BB + b) * O4 + o4] = a;
    }
    grid_bar(base, 3);

    // ---- Phase 4: g_OV = sigmoid(gate) * sum_p POV[p]  (8192 outputs) ----
    if (bid < 32) {
        int e  = bid * NT + tid;
        int bb = e >> 11;
        int o  = e & (D_MODEL - 1);
        float s = 0.f;
        #pragma unroll
        for (int p = 0; p < NKV; ++p)
            s += g_POV[((size_t)p * BB + bb) * D_MODEL + o];
        const float gv = *gate;
        g_OV[e] = s * (1.f / (1.f + expf(-gv)));
    }
    grid_bar(base, 4);

    // ---- Phase 5: out = lh + ov (268 MB stream, static balanced split) ----
    // 2 rows per iteration: 4 front-batched loads, then 4 stores (MLP_p1=4).
    {
        const int start = bid * RPB_LO + (bid < RPB_REM ? bid : RPB_REM);
        const int count = RPB_LO + (bid < RPB_REM ? 1 : 0);

        const float4* OV4 = reinterpret_cast<const float4*>(g_OV);
        const float4* LH  = reinterpret_cast<const float4*>(lh);
        float4*       O   = reinterpret_cast<float4*>(out);

        int r = 0;
        size_t idx = (size_t)start * O4 + tid;
        #pragma unroll 2
        for (; r + 2 <= count; r += 2) {
            const int row0 = start + r;
            const int cb0  = row0 >> 12;
            const int cb1  = (row0 + 1) >> 12;

            float4 x0 = LH[idx];
            float4 x1 = LH[idx + NT];
            float4 x2 = LH[idx + O4];
            float4 x3 = LH[idx + O4 + NT];

            const float4 a0 = OV4[cb0 * O4 + tid];
            const float4 a1 = OV4[cb0 * O4 + tid + NT];
            const float4 a2 = OV4[cb1 * O4 + tid];
            const float4 a3 = OV4[cb1 * O4 + tid + NT];

            x0.x += a0.x; x0.y += a0.y; x0.z += a0.z; x0.w += a0.w;
            x1.x += a1.x; x1.y += a1.y; x1.z += a1.z; x1.w += a1.w;
            x2.x += a2.x; x2.y += a2.y; x2.z += a2.z; x2.w += a2.w;
            x3.x += a3.x; x3.y += a3.y; x3.z += a3.z; x3.w += a3.w;

            O[idx]           = x0;
            O[idx + NT]      = x1;
            O[idx + O4]      = x2;
            O[idx + O4 + NT] = x3;
            idx += 2 * O4;
        }
        if (r < count) {                 // odd tail row
            const int row = start + r;
            const int cb  = row >> 12;
            const float4 a0 = OV4[cb * O4 + tid];
            const float4 a1 = OV4[cb * O4 + tid + NT];
            float4 x0 = LH[idx];
            float4 x1 = LH[idx + NT];
            x0.x += a0.x; x0.y += a0.y; x0.z += a0.z; x0.w += a0.w;
            x1.x += a1.x; x1.y += a1.y; x1.z += a1.z; x1.w += a1.w;
            O[idx]      = x0;
            O[idx + NT] = x1;
        }
    }
}

// ---------------------------------------------------------------------------
// Input order: 0 last_hidden, 1 zH, 2 W_mem, 3 W_q, 4 W_k, 5 W_v, 6 W_o, 7 gate
// ---------------------------------------------------------------------------
extern "C" void kernel_launch(void* const* d_in, const int* in_sizes, int n_in,
                              void* d_out, int out_size) {
    const float* lh   = (const float*)d_in[0];
    const float* zH   = (const float*)d_in[1];
    const float* Wm   = (const float*)d_in[2];
    const float* Wv   = (const float*)d_in[5];
    const float* Wo   = (const float*)d_in[6];
    const float* gate = (const float*)d_in[7];
    float* out = (float*)d_out;

    k_fused<<<G, NT>>>(lh, zH, Wm, Wv, Wo, gate, out);
}